// round 1
// baseline (speedup 1.0000x reference)
#include <cuda_runtime.h>

// ============================================================================
// EdgeMLP: f = MLP(edges[:, :3]) -> masked pairwise cosine similarity matrix
//   out[i][j] = (cls1[i]==cls2[j]) ? dot(f1n[i], f2n[j]) : 0
// where f1n/f2n are L2-normalized 32-d features.
// ============================================================================

#define N_MAX 8192
#define KK 32

// Scratch (allocation-free): normalized features + integer class labels
__device__ float g_f1[N_MAX * KK];
__device__ float g_f2[N_MAX * KK];
__device__ int   g_c1[N_MAX];
__device__ int   g_c2[N_MAX];

// ----------------------------------------------------------------------------
// Kernel 1: per-row MLP + normalization.  One thread per row.
// W1: [3][64] row-major, b1: [64], W2: [64][32] row-major, b2: [32]
// ----------------------------------------------------------------------------
__global__ void feat_kernel(const float* __restrict__ edges, int N,
                            const float* __restrict__ W1, const float* __restrict__ b1,
                            const float* __restrict__ W2, const float* __restrict__ b2,
                            int which)
{
    __shared__ float sW1[192], sb1[64], sW2[2048], sb2[32];
    int t = threadIdx.x;
    for (int i = t; i < 192;  i += blockDim.x) sW1[i] = W1[i];
    for (int i = t; i < 64;   i += blockDim.x) sb1[i] = b1[i];
    for (int i = t; i < 2048; i += blockDim.x) sW2[i] = W2[i];
    for (int i = t; i < 32;   i += blockDim.x) sb2[i] = b2[i];
    __syncthreads();

    int row = blockIdx.x * blockDim.x + t;
    if (row >= N) return;

    float4 e = reinterpret_cast<const float4*>(edges)[row];  // x0,x1,x2,cls

    float f[32];
    #pragma unroll
    for (int o = 0; o < 32; o++) f[o] = sb2[o];

    #pragma unroll 4
    for (int k = 0; k < 64; k++) {
        float h = fmaf(e.x, sW1[k], fmaf(e.y, sW1[64 + k], fmaf(e.z, sW1[128 + k], sb1[k])));
        h = fmaxf(h, 0.0f);
        const float4* w2r = reinterpret_cast<const float4*>(&sW2[k * 32]);
        #pragma unroll
        for (int q = 0; q < 8; q++) {
            float4 w = w2r[q];
            f[q * 4 + 0] = fmaf(h, w.x, f[q * 4 + 0]);
            f[q * 4 + 1] = fmaf(h, w.y, f[q * 4 + 1]);
            f[q * 4 + 2] = fmaf(h, w.z, f[q * 4 + 2]);
            f[q * 4 + 3] = fmaf(h, w.w, f[q * 4 + 3]);
        }
    }

    float s = 0.0f;
    #pragma unroll
    for (int o = 0; o < 32; o++) s = fmaf(f[o], f[o], s);
    float inv = 1.0f / fmaxf(sqrtf(s), 1e-20f);

    float* fout = which ? g_f2 : g_f1;
    int*   cout = which ? g_c2 : g_c1;
    float4* fo = reinterpret_cast<float4*>(fout + row * KK);
    #pragma unroll
    for (int q = 0; q < 8; q++) {
        float4 v;
        v.x = f[q * 4 + 0] * inv;
        v.y = f[q * 4 + 1] * inv;
        v.z = f[q * 4 + 2] * inv;
        v.w = f[q * 4 + 3] * inv;
        fo[q] = v;
    }
    cout[row] = (int)e.w;
}

// ----------------------------------------------------------------------------
// Packed fp32x2 helpers (Blackwell sm_100+ only; doubles FFMA throughput)
// ----------------------------------------------------------------------------
__device__ __forceinline__ unsigned long long pack2(float a, float b) {
    unsigned long long r;
    asm("mov.b64 %0, {%1, %2};" : "=l"(r) : "f"(a), "f"(b));
    return r;
}
__device__ __forceinline__ void unpack2(unsigned long long v, float& a, float& b) {
    asm("mov.b64 {%0, %1}, %2;" : "=f"(a), "=f"(b) : "l"(v));
}
__device__ __forceinline__ void fma2(unsigned long long& c, unsigned long long a, unsigned long long b) {
    asm("fma.rn.f32x2 %0, %1, %2, %0;" : "+l"(c) : "l"(a), "l"(b));
}

// ----------------------------------------------------------------------------
// Kernel 2: 128x128 tile GEMM (K=32 resident) + class mask epilogue.
// 256 threads, 8x8 micro-tile per thread, f32x2 packed accumulators.
// ----------------------------------------------------------------------------
#define BM 128
#define BN 128
#define PAD 4

__global__ void __launch_bounds__(256, 2) pair_kernel(float* __restrict__ out, int N1, int N2)
{
    __shared__ float As[KK][BM + PAD];   // As[k][i]  (transposed: k-major)
    __shared__ float Bs[KK][BN + PAD];   // Bs[k][j]
    __shared__ int sc1[BM];
    __shared__ int sc2[BN];

    int t  = threadIdx.x;
    int i0 = blockIdx.y * BM;
    int j0 = blockIdx.x * BN;

    // Load tiles, transposing row-major [row][32] -> [k][row]
    #pragma unroll
    for (int p = 0; p < 4; p++) {
        int v   = t + p * 256;        // 0..1023 float4 slots
        int row = v >> 3;
        int q   = v & 7;
        float4 a = reinterpret_cast<const float4*>(g_f1 + (size_t)(i0 + row) * KK)[q];
        As[q * 4 + 0][row] = a.x;
        As[q * 4 + 1][row] = a.y;
        As[q * 4 + 2][row] = a.z;
        As[q * 4 + 3][row] = a.w;
        float4 b = reinterpret_cast<const float4*>(g_f2 + (size_t)(j0 + row) * KK)[q];
        Bs[q * 4 + 0][row] = b.x;
        Bs[q * 4 + 1][row] = b.y;
        Bs[q * 4 + 2][row] = b.z;
        Bs[q * 4 + 3][row] = b.w;
    }
    if (t < BM) sc1[t] = g_c1[i0 + t];
    else        sc2[t - BM] = g_c2[j0 + (t - BM)];
    __syncthreads();

    int ty = t >> 4;          // 0..15
    int tx = t & 15;          // 0..15
    int ai = ty * 8;
    int bj = tx * 8;

    unsigned long long acc[8][4];
    #pragma unroll
    for (int m = 0; m < 8; m++)
        #pragma unroll
        for (int n = 0; n < 4; n++) acc[m][n] = 0ULL;

    #pragma unroll
    for (int k = 0; k < KK; k++) {
        float4 a0 = *reinterpret_cast<const float4*>(&As[k][ai]);
        float4 a1 = *reinterpret_cast<const float4*>(&As[k][ai + 4]);
        // b fragments come out of smem already packed as f32x2 pairs
        ulonglong2 bq0 = *reinterpret_cast<const ulonglong2*>(&Bs[k][bj]);
        ulonglong2 bq1 = *reinterpret_cast<const ulonglong2*>(&Bs[k][bj + 4]);

        unsigned long long ap[8];
        ap[0] = pack2(a0.x, a0.x);
        ap[1] = pack2(a0.y, a0.y);
        ap[2] = pack2(a0.z, a0.z);
        ap[3] = pack2(a0.w, a0.w);
        ap[4] = pack2(a1.x, a1.x);
        ap[5] = pack2(a1.y, a1.y);
        ap[6] = pack2(a1.z, a1.z);
        ap[7] = pack2(a1.w, a1.w);

        #pragma unroll
        for (int m = 0; m < 8; m++) {
            fma2(acc[m][0], ap[m], bq0.x);
            fma2(acc[m][1], ap[m], bq0.y);
            fma2(acc[m][2], ap[m], bq1.x);
            fma2(acc[m][3], ap[m], bq1.y);
        }
    }

    // Epilogue: class-equality mask, float4 coalesced stores
    int cn0 = sc2[bj + 0], cn1 = sc2[bj + 1], cn2 = sc2[bj + 2], cn3 = sc2[bj + 3];
    int cn4 = sc2[bj + 4], cn5 = sc2[bj + 5], cn6 = sc2[bj + 6], cn7 = sc2[bj + 7];

    #pragma unroll
    for (int m = 0; m < 8; m++) {
        int cm = sc1[ai + m];
        float v0, v1, v2, v3, v4, v5, v6, v7;
        unpack2(acc[m][0], v0, v1);
        unpack2(acc[m][1], v2, v3);
        unpack2(acc[m][2], v4, v5);
        unpack2(acc[m][3], v6, v7);
        float4 o0, o1;
        o0.x = (cm == cn0) ? v0 : 0.0f;
        o0.y = (cm == cn1) ? v1 : 0.0f;
        o0.z = (cm == cn2) ? v2 : 0.0f;
        o0.w = (cm == cn3) ? v3 : 0.0f;
        o1.x = (cm == cn4) ? v4 : 0.0f;
        o1.y = (cm == cn5) ? v5 : 0.0f;
        o1.z = (cm == cn6) ? v6 : 0.0f;
        o1.w = (cm == cn7) ? v7 : 0.0f;
        float* orow = out + (size_t)(i0 + ai + m) * (size_t)N2 + (size_t)(j0 + bj);
        reinterpret_cast<float4*>(orow)[0] = o0;
        reinterpret_cast<float4*>(orow)[1] = o1;
    }
}

// ----------------------------------------------------------------------------
extern "C" void kernel_launch(void* const* d_in, const int* in_sizes, int n_in,
                              void* d_out, int out_size)
{
    const float* edges1 = (const float*)d_in[0];
    const float* edges2 = (const float*)d_in[1];
    const float* W1     = (const float*)d_in[2];
    const float* b1     = (const float*)d_in[3];
    const float* W2     = (const float*)d_in[4];
    const float* b2     = (const float*)d_in[5];
    float* out = (float*)d_out;

    int N1 = in_sizes[0] / 4;
    int N2 = in_sizes[1] / 4;

    feat_kernel<<<(N1 + 255) / 256, 256>>>(edges1, N1, W1, b1, W2, b2, 0);
    feat_kernel<<<(N2 + 255) / 256, 256>>>(edges2, N2, W1, b1, W2, b2, 1);

    dim3 grid(N2 / BN, N1 / BM);
    pair_kernel<<<grid, 256>>>(out, N1, N2);
}

// round 3
// speedup vs baseline: 1.9806x; 1.9806x over previous
#include <cuda_runtime.h>
#include <cuda_fp16.h>
#include <cstdint>

// ============================================================================
// EdgeMLP: f = MLP(edges[:, :3]); out[i][j] = (cls1[i]==cls2[j]) * cos(f1[i],f2[j])
// Round 3: mma.sync (HMMA m16n8k16, fp16 in / fp32 acc) — no sm_103a-gated PTX.
// ============================================================================

#define N_MAX 8192
#define KK 32

// Scratch (allocation-free): L2-normalized fp16 features + int class labels
__device__ __half g_h1[N_MAX * KK];
__device__ __half g_h2[N_MAX * KK];
__device__ int    g_c1[N_MAX];
__device__ int    g_c2[N_MAX];

// ----------------------------------------------------------------------------
// Kernel 1: MLP + normalize, 4 threads per row (each handles 8 of 32 outputs).
// Covers both edge sets in one launch.
// ----------------------------------------------------------------------------
__global__ void __launch_bounds__(256) feat_kernel(
    const float* __restrict__ e1, const float* __restrict__ e2, int N1, int N2,
    const float* __restrict__ W1, const float* __restrict__ b1,
    const float* __restrict__ W2, const float* __restrict__ b2)
{
    __shared__ float sW1[192], sb1[64], sW2[2048], sb2[32];
    int t = threadIdx.x;
    for (int i = t; i < 192;  i += 256) sW1[i] = W1[i];
    if (t < 64) sb1[t] = b1[t];
    for (int i = t; i < 2048; i += 256) sW2[i] = W2[i];
    if (t < 32) sb2[t] = b2[t];
    __syncthreads();

    int gid  = blockIdx.x * 256 + t;
    int row2 = gid >> 2;
    int s    = gid & 3;               // output slice: cols [8s, 8s+8)
    if (row2 >= N1 + N2) return;

    const float* ed; __half* fo; int* co; int row;
    if (row2 < N1) { ed = e1; fo = g_h1; co = g_c1; row = row2; }
    else           { ed = e2; fo = g_h2; co = g_c2; row = row2 - N1; }

    float4 e = reinterpret_cast<const float4*>(ed)[row];

    float f[8];
    #pragma unroll
    for (int q = 0; q < 8; q++) f[q] = sb2[s * 8 + q];

    #pragma unroll 8
    for (int k = 0; k < 64; k++) {
        float h = fmaf(e.x, sW1[k], fmaf(e.y, sW1[64 + k], fmaf(e.z, sW1[128 + k], sb1[k])));
        h = fmaxf(h, 0.0f);
        const float4* w = reinterpret_cast<const float4*>(&sW2[k * 32 + s * 8]);
        float4 w0 = w[0], w1 = w[1];
        f[0] = fmaf(h, w0.x, f[0]); f[1] = fmaf(h, w0.y, f[1]);
        f[2] = fmaf(h, w0.z, f[2]); f[3] = fmaf(h, w0.w, f[3]);
        f[4] = fmaf(h, w1.x, f[4]); f[5] = fmaf(h, w1.y, f[5]);
        f[6] = fmaf(h, w1.z, f[6]); f[7] = fmaf(h, w1.w, f[7]);
    }

    float p = 0.0f;
    #pragma unroll
    for (int q = 0; q < 8; q++) p = fmaf(f[q], f[q], p);
    p += __shfl_xor_sync(0xFFFFFFFFu, p, 1);
    p += __shfl_xor_sync(0xFFFFFFFFu, p, 2);
    float inv = rsqrtf(fmaxf(p, 1e-24f));

    __half2 o[4];
    #pragma unroll
    for (int q = 0; q < 4; q++)
        o[q] = __floats2half2_rn(f[2 * q] * inv, f[2 * q + 1] * inv);
    *reinterpret_cast<uint4*>(fo + (size_t)row * KK + s * 8) = *reinterpret_cast<uint4*>(o);
    if (s == 0) co[row] = (int)e.w;
}

// ----------------------------------------------------------------------------
// HMMA m16n8k16: D(f32) = A(f16, row-major) * B(f16, col-major) + D
// ----------------------------------------------------------------------------
__device__ __forceinline__ void hmma16816(float c[4], const uint32_t a[4], const uint32_t b[2]) {
    asm volatile(
        "mma.sync.aligned.m16n8k16.row.col.f32.f16.f16.f32 "
        "{%0,%1,%2,%3}, {%4,%5,%6,%7}, {%8,%9}, {%0,%1,%2,%3};"
        : "+f"(c[0]), "+f"(c[1]), "+f"(c[2]), "+f"(c[3])
        : "r"(a[0]), "r"(a[1]), "r"(a[2]), "r"(a[3]), "r"(b[0]), "r"(b[1]));
}

// ----------------------------------------------------------------------------
// Kernel 2: 128x128 output tile per CTA. 256 threads = 8 warps, each warp
// computes a 64x32 sub-tile (warp grid 2 M x 4 N) via m16n8k16.
// Smem rows padded to 40 halves (80B) -> conflict-free half2 fragment loads.
// ----------------------------------------------------------------------------
#define RS 40   // smem row stride in halves

__global__ void __launch_bounds__(256, 2) pair_kernel(float* __restrict__ out, int N2)
{
    __shared__ __half As[128][RS];
    __shared__ __half Bs[128][RS];
    __shared__ int sc1[128], sc2[128];

    int t    = threadIdx.x;
    int wid  = t >> 5;
    int lane = t & 31;
    int i0   = blockIdx.y * 128;
    int j0   = blockIdx.x * 128;

    // --- Load tiles: 128 rows x 64B each (uint4 chunks) ---
    #pragma unroll
    for (int p = 0; p < 2; p++) {
        int chunk = t + p * 256;          // 0..511
        int row   = chunk >> 2;
        int c16   = chunk & 3;
        uint4 a = reinterpret_cast<const uint4*>(g_h1 + (size_t)(i0 + row) * KK)[c16];
        *reinterpret_cast<uint4*>(&As[row][c16 * 8]) = a;
        uint4 b = reinterpret_cast<const uint4*>(g_h2 + (size_t)(j0 + row) * KK)[c16];
        *reinterpret_cast<uint4*>(&Bs[row][c16 * 8]) = b;
    }
    if (t < 128) sc1[t] = g_c1[i0 + t];
    else         sc2[t - 128] = g_c2[j0 + (t - 128)];
    __syncthreads();

    int warp_m = wid >> 2;     // 0..1  -> 64-row slab
    int warp_n = wid & 3;      // 0..3  -> 32-col slab
    int r4 = lane >> 2;        // 0..7
    int c2 = (lane & 3) * 2;   // 0,2,4,6

    float acc[4][4][4];
    #pragma unroll
    for (int mt = 0; mt < 4; mt++)
        #pragma unroll
        for (int nt = 0; nt < 4; nt++)
            #pragma unroll
            for (int q = 0; q < 4; q++) acc[mt][nt][q] = 0.0f;

    #pragma unroll
    for (int k = 0; k < 2; k++) {                  // two K=16 steps
        int kc = c2 + k * 16;

        uint32_t af[4][4];
        #pragma unroll
        for (int mt = 0; mt < 4; mt++) {
            int row = warp_m * 64 + mt * 16 + r4;
            af[mt][0] = *reinterpret_cast<const uint32_t*>(&As[row    ][kc    ]);
            af[mt][1] = *reinterpret_cast<const uint32_t*>(&As[row + 8][kc    ]);
            af[mt][2] = *reinterpret_cast<const uint32_t*>(&As[row    ][kc + 8]);
            af[mt][3] = *reinterpret_cast<const uint32_t*>(&As[row + 8][kc + 8]);
        }
        uint32_t bf[4][2];
        #pragma unroll
        for (int nt = 0; nt < 4; nt++) {
            int col = warp_n * 32 + nt * 8 + r4;
            bf[nt][0] = *reinterpret_cast<const uint32_t*>(&Bs[col][kc    ]);
            bf[nt][1] = *reinterpret_cast<const uint32_t*>(&Bs[col][kc + 8]);
        }

        #pragma unroll
        for (int mt = 0; mt < 4; mt++)
            #pragma unroll
            for (int nt = 0; nt < 4; nt++)
                hmma16816(acc[mt][nt], af[mt], bf[nt]);
    }

    // --- Epilogue: class mask + float2 stores (full 32B sectors per row) ---
    int cn[4][2];
    #pragma unroll
    for (int nt = 0; nt < 4; nt++) {
        cn[nt][0] = sc2[warp_n * 32 + nt * 8 + c2];
        cn[nt][1] = sc2[warp_n * 32 + nt * 8 + c2 + 1];
    }

    #pragma unroll
    for (int mt = 0; mt < 4; mt++) {
        int row0 = warp_m * 64 + mt * 16 + r4;
        #pragma unroll
        for (int h = 0; h < 2; h++) {
            int row = row0 + h * 8;
            int cm  = sc1[row];
            float* orow = out + (size_t)(i0 + row) * (size_t)N2
                              + (size_t)(j0 + warp_n * 32 + c2);
            #pragma unroll
            for (int nt = 0; nt < 4; nt++) {
                float2 o;
                o.x = (cm == cn[nt][0]) ? acc[mt][nt][h * 2]     : 0.0f;
                o.y = (cm == cn[nt][1]) ? acc[mt][nt][h * 2 + 1] : 0.0f;
                *reinterpret_cast<float2*>(orow + nt * 8) = o;
            }
        }
    }
}

// ----------------------------------------------------------------------------
extern "C" void kernel_launch(void* const* d_in, const int* in_sizes, int n_in,
                              void* d_out, int out_size)
{
    const float* edges1 = (const float*)d_in[0];
    const float* edges2 = (const float*)d_in[1];
    const float* W1     = (const float*)d_in[2];
    const float* b1     = (const float*)d_in[3];
    const float* W2     = (const float*)d_in[4];
    const float* b2     = (const float*)d_in[5];
    float* out = (float*)d_out;

    int N1 = in_sizes[0] / 4;
    int N2 = in_sizes[1] / 4;

    int totalThreads = (N1 + N2) * 4;
    feat_kernel<<<(totalThreads + 255) / 256, 256>>>(edges1, edges2, N1, N2, W1, b1, W2, b2);

    dim3 grid(N2 / 128, N1 / 128);
    pair_kernel<<<grid, 256>>>(out, N2);
}